// round 1
// baseline (speedup 1.0000x reference)
#include <cuda_runtime.h>
#include <math_constants.h>

// Problem constants
#define BB   16
#define DD   1024
#define TT   4096
#define CDIM 8
#define CSZ  1024

#define TILE     128               // t-positions per block
#define NTHREADS 128
#define TILES_PER_B (TT / TILE)    // 32
#define NBLOCKS (BB * TILES_PER_B) // 512

// Output layout (concatenated float32, reference return order):
// out [B,D,T], commitment_loss [B], codebook_loss [B], indices [B,T], z_e [B,CD,T]
#define OFF_OUT 0
#define OFF_CL  (BB * DD * TT)                 // 67108864
#define OFF_CB  (OFF_CL + BB)                  // 67108880
#define OFF_IDX (OFF_CB + BB)                  // 67108896
#define OFF_ZE  (OFF_IDX + BB * TT)            // 67174432

// Scratch (no allocations allowed -> device globals)
__device__ float g_winT[DD * CDIM];     // in-proj weight, transposed [d][o]
__device__ float g_wout[DD * CDIM];     // out-proj weight [d][c]
__device__ float g_cbn[CSZ * CDIM];     // normalized codebook [c][k]
__device__ float g_losspart[NBLOCKS];   // per-block loss partials

// ---------------------------------------------------------------------------
// Prep A: weight-norm of in_proj (row norm over D=1024), store transposed.
// One block per output row o (8 blocks).
// ---------------------------------------------------------------------------
__global__ void prep_win(const float* __restrict__ v, const float* __restrict__ g) {
    int o = blockIdx.x;
    __shared__ float red[256];
    float s = 0.f;
    for (int d = threadIdx.x; d < DD; d += blockDim.x) {
        float x = v[o * DD + d];
        s = fmaf(x, x, s);
    }
    red[threadIdx.x] = s;
    __syncthreads();
    for (int off = 128; off > 0; off >>= 1) {
        if (threadIdx.x < off) red[threadIdx.x] += red[threadIdx.x + off];
        __syncthreads();
    }
    float scale = g[o] / sqrtf(red[0]);
    for (int d = threadIdx.x; d < DD; d += blockDim.x) {
        g_winT[d * CDIM + o] = v[o * DD + d] * scale;
    }
}

// ---------------------------------------------------------------------------
// Prep B: weight-norm of out_proj rows (norm over CD=8) and l2-normalized
// codebook rows. One thread per row.
// ---------------------------------------------------------------------------
__global__ void prep_rows(const float* __restrict__ wov, const float* __restrict__ wog,
                          const float* __restrict__ cb) {
    int i = blockIdx.x * blockDim.x + threadIdx.x;
    if (i < DD) {
        float vv[CDIM];
        float s = 0.f;
#pragma unroll
        for (int c = 0; c < CDIM; c++) { vv[c] = wov[i * CDIM + c]; s = fmaf(vv[c], vv[c], s); }
        float sc = wog[i] / sqrtf(s);
#pragma unroll
        for (int c = 0; c < CDIM; c++) g_wout[i * CDIM + c] = vv[c] * sc;
    }
    if (i < CSZ) {
        float vv[CDIM];
        float s = 0.f;
#pragma unroll
        for (int k = 0; k < CDIM; k++) { vv[k] = cb[i * CDIM + k]; s = fmaf(vv[k], vv[k], s); }
        float n = fmaxf(sqrtf(s), 1e-12f);
        float inv = 1.f / n;
#pragma unroll
        for (int k = 0; k < CDIM; k++) g_cbn[i * CDIM + k] = vv[k] * inv;
    }
}

// ---------------------------------------------------------------------------
// Main fused kernel: in-proj -> argmax (cosine NN) -> gather -> loss partial
// -> out-proj. One thread owns one (b, t) column.
// The 32KB smem buffer is time-shared: winT -> cbn -> wout.
// ---------------------------------------------------------------------------
__global__ void __launch_bounds__(NTHREADS)
vq_main(const float* __restrict__ z,
        const float* __restrict__ in_b,
        const float* __restrict__ out_b,
        const float* __restrict__ codebook,
        float* __restrict__ out) {
    __shared__ float4 s_w[DD * 2];    // 32 KB: [row][2 x float4] = 8 floats/row
    __shared__ float  s_bout[DD];     // 4 KB
    __shared__ float  s_red[NTHREADS / 32];

    const int blk  = blockIdx.x;
    const int b    = blk / TILES_PER_B;
    const int tile = blk % TILES_PER_B;
    const int t    = tile * TILE + threadIdx.x;

    // --- load in-proj weight (transposed) into smem ---
    {
        const float4* src = (const float4*)g_winT;
        for (int i = threadIdx.x; i < DD * 2; i += NTHREADS) s_w[i] = src[i];
    }
    __syncthreads();

    // --- phase 1: z_e[o] = sum_d winT[d][o] * z[b,d,t] + bias ---
    float acc[CDIM];
#pragma unroll
    for (int o = 0; o < CDIM; o++) acc[o] = 0.f;

    const float* zp = z + (size_t)b * (DD * TT) + t;
#pragma unroll 4
    for (int d = 0; d < DD; d++) {
        float zv = __ldg(zp + (size_t)d * TT);
        float4 wa = s_w[2 * d];
        float4 wb = s_w[2 * d + 1];
        acc[0] = fmaf(zv, wa.x, acc[0]);
        acc[1] = fmaf(zv, wa.y, acc[1]);
        acc[2] = fmaf(zv, wa.z, acc[2]);
        acc[3] = fmaf(zv, wa.w, acc[3]);
        acc[4] = fmaf(zv, wb.x, acc[4]);
        acc[5] = fmaf(zv, wb.y, acc[5]);
        acc[6] = fmaf(zv, wb.z, acc[6]);
        acc[7] = fmaf(zv, wb.w, acc[7]);
    }
    float ze[CDIM];
#pragma unroll
    for (int o = 0; o < CDIM; o++) ze[o] = acc[o] + __ldg(in_b + o);

    // write z_e output [B, CD, T]
    {
        float* zeout = out + OFF_ZE + (size_t)b * (CDIM * TT) + t;
#pragma unroll
        for (int o = 0; o < CDIM; o++) zeout[(size_t)o * TT] = ze[o];
    }

    __syncthreads();  // done reading winT

    // --- load normalized codebook into smem ---
    {
        const float4* src = (const float4*)g_cbn;
        for (int i = threadIdx.x; i < CSZ * 2; i += NTHREADS) s_w[i] = src[i];
    }
    __syncthreads();

    // --- phase 2: argmax_c ( z_e . cbn[c] )  ===  argmin cosine distance ---
    float best = -CUDART_INF_F;
    int bi = 0;
#pragma unroll 4
    for (int c = 0; c < CSZ; c++) {
        float4 ca = s_w[2 * c];
        float4 cb2 = s_w[2 * c + 1];
        float dot = ze[0] * ca.x;
        dot = fmaf(ze[1], ca.y, dot);
        dot = fmaf(ze[2], ca.z, dot);
        dot = fmaf(ze[3], ca.w, dot);
        dot = fmaf(ze[4], cb2.x, dot);
        dot = fmaf(ze[5], cb2.y, dot);
        dot = fmaf(ze[6], cb2.z, dot);
        dot = fmaf(ze[7], cb2.w, dot);
        if (dot > best) { best = dot; bi = c; }   // strict > keeps first (jnp.argmax)
    }
    out[OFF_IDX + (size_t)b * TT + t] = (float)bi;

    // gather raw codebook row (32KB table -> L2 resident)
    float zq[CDIM];
    {
        const float4* cb4 = (const float4*)codebook;
        float4 q0 = __ldg(cb4 + 2 * bi);
        float4 q1 = __ldg(cb4 + 2 * bi + 1);
        zq[0] = q0.x; zq[1] = q0.y; zq[2] = q0.z; zq[3] = q0.w;
        zq[4] = q1.x; zq[5] = q1.y; zq[6] = q1.z; zq[7] = q1.w;
    }

    // --- loss partial: sum (z_e - z_q)^2 over this thread's column ---
    float ls = 0.f;
#pragma unroll
    for (int o = 0; o < CDIM; o++) {
        float d = ze[o] - zq[o];
        ls = fmaf(d, d, ls);
    }
#pragma unroll
    for (int off = 16; off > 0; off >>= 1)
        ls += __shfl_down_sync(0xffffffffu, ls, off);
    if ((threadIdx.x & 31) == 0) s_red[threadIdx.x >> 5] = ls;
    __syncthreads();  // also guards s_w reuse below
    if (threadIdx.x == 0) {
        float tot = 0.f;
#pragma unroll
        for (int w = 0; w < NTHREADS / 32; w++) tot += s_red[w];
        g_losspart[blk] = tot;   // deterministic: one writer per slot
    }

    // --- load out-proj weight + bias into smem ---
    {
        const float4* src = (const float4*)g_wout;
        for (int i = threadIdx.x; i < DD * 2; i += NTHREADS) s_w[i] = src[i];
        for (int i = threadIdx.x; i < DD; i += NTHREADS) s_bout[i] = out_b[i];
    }
    __syncthreads();

    // --- phase 3: out[b,d,t] = wout[d] . z_q + bias[d]  (z_q_st == z_q fwd) ---
    float* op = out + (size_t)b * (DD * TT) + t;
#pragma unroll 4
    for (int d = 0; d < DD; d++) {
        float4 wa = s_w[2 * d];
        float4 wb = s_w[2 * d + 1];
        float v = s_bout[d];
        v = fmaf(zq[0], wa.x, v);
        v = fmaf(zq[1], wa.y, v);
        v = fmaf(zq[2], wa.z, v);
        v = fmaf(zq[3], wa.w, v);
        v = fmaf(zq[4], wb.x, v);
        v = fmaf(zq[5], wb.y, v);
        v = fmaf(zq[6], wb.z, v);
        v = fmaf(zq[7], wb.w, v);
        op[(size_t)d * TT] = v;
    }
}

// ---------------------------------------------------------------------------
// Finish: deterministic fixed-order loss reduction. commitment == codebook
// loss numerically (same squared diff), write both.
// ---------------------------------------------------------------------------
__global__ void vq_finish(float* __restrict__ out) {
    int b = threadIdx.x;
    if (b < BB) {
        float s = 0.f;
        for (int i = 0; i < TILES_PER_B; i++) s += g_losspart[b * TILES_PER_B + i];
        s *= (1.0f / (float)(CDIM * TT));
        out[OFF_CL + b] = s;
        out[OFF_CB + b] = s;
    }
}

extern "C" void kernel_launch(void* const* d_in, const int* in_sizes, int n_in,
                              void* d_out, int out_size) {
    const float* z   = (const float*)d_in[0];
    const float* ipv = (const float*)d_in[1];
    const float* ipg = (const float*)d_in[2];
    const float* ipb = (const float*)d_in[3];
    const float* opv = (const float*)d_in[4];
    const float* opg = (const float*)d_in[5];
    const float* opb = (const float*)d_in[6];
    const float* cb  = (const float*)d_in[7];
    float* out = (float*)d_out;

    prep_win<<<CDIM, 256>>>(ipv, ipg);
    prep_rows<<<(CSZ + 255) / 256, 256>>>(opv, opg, cb);
    vq_main<<<NBLOCKS, NTHREADS>>>(z, ipb, opb, cb, out);
    vq_finish<<<1, 32>>>(out);
}

// round 2
// speedup vs baseline: 1.4191x; 1.4191x over previous
#include <cuda_runtime.h>
#include <math_constants.h>

// Problem constants
#define BB   16
#define DD   1024
#define TT   4096
#define CDIM 8
#define CSZ  1024

#define TILE     128               // t-positions per block
#define NTHREADS 256               // 2 halves x TILE threads
#define HALF     512               // d's / codes per half
#define TILES_PER_B (TT / TILE)    // 32
#define NBLOCKS (BB * TILES_PER_B) // 512

// Output layout (concatenated float32, reference return order):
// out [B,D,T], commitment_loss [B], codebook_loss [B], indices [B,T], z_e [B,CD,T]
#define OFF_OUT 0
#define OFF_CL  (BB * DD * TT)
#define OFF_CB  (OFF_CL + BB)
#define OFF_IDX (OFF_CB + BB)
#define OFF_ZE  (OFF_IDX + BB * TT)

// Scratch (no allocations allowed -> device globals)
__device__ float g_winT[DD * CDIM];     // in-proj weight, transposed [d][o] (o-pairs natural)
__device__ float g_wout2[DD * CDIM];    // out-proj weight, pair-interleaved by d:
                                        //   g_wout2[(d/2)*16 + k*2 + (d&1)] = w[d][k]
__device__ float g_cbn2[CSZ * CDIM];    // normalized codebook, pair-interleaved by c:
                                        //   g_cbn2[(c/2)*16 + k*2 + (c&1)] = cbn[c][k]
__device__ float g_losspart[NBLOCKS];

// ---------------- f32x2 packed helpers ----------------
typedef unsigned long long u64;

__device__ __forceinline__ u64 pk(float lo, float hi) {
    u64 r; asm("mov.b64 %0, {%1, %2};" : "=l"(r) : "f"(lo), "f"(hi)); return r;
}
__device__ __forceinline__ void upk(float& lo, float& hi, u64 v) {
    asm("mov.b64 {%0, %1}, %2;" : "=f"(lo), "=f"(hi) : "l"(v));
}
__device__ __forceinline__ u64 f2(u64 a, u64 b, u64 c) {
    u64 d; asm("fma.rn.f32x2 %0, %1, %2, %3;" : "=l"(d) : "l"(a), "l"(b), "l"(c)); return d;
}

// ---------------------------------------------------------------------------
// Prep A: weight-norm of in_proj (row norm over D=1024), store transposed.
// ---------------------------------------------------------------------------
__global__ void prep_win(const float* __restrict__ v, const float* __restrict__ g) {
    int o = blockIdx.x;
    __shared__ float red[256];
    float s = 0.f;
    for (int d = threadIdx.x; d < DD; d += blockDim.x) {
        float x = v[o * DD + d];
        s = fmaf(x, x, s);
    }
    red[threadIdx.x] = s;
    __syncthreads();
    for (int off = 128; off > 0; off >>= 1) {
        if (threadIdx.x < off) red[threadIdx.x] += red[threadIdx.x + off];
        __syncthreads();
    }
    float scale = g[o] / sqrtf(red[0]);
    for (int d = threadIdx.x; d < DD; d += blockDim.x) {
        g_winT[d * CDIM + o] = v[o * DD + d] * scale;
    }
}

// ---------------------------------------------------------------------------
// Prep B: weight-norm out_proj rows + l2-normalized codebook, pair-interleaved.
// ---------------------------------------------------------------------------
__global__ void prep_rows(const float* __restrict__ wov, const float* __restrict__ wog,
                          const float* __restrict__ cb) {
    int i = blockIdx.x * blockDim.x + threadIdx.x;
    if (i < DD) {
        float vv[CDIM];
        float s = 0.f;
#pragma unroll
        for (int c = 0; c < CDIM; c++) { vv[c] = wov[i * CDIM + c]; s = fmaf(vv[c], vv[c], s); }
        float sc = wog[i] / sqrtf(s);
#pragma unroll
        for (int c = 0; c < CDIM; c++)
            g_wout2[(i >> 1) * 16 + c * 2 + (i & 1)] = vv[c] * sc;
    }
    if (i < CSZ) {
        float vv[CDIM];
        float s = 0.f;
#pragma unroll
        for (int k = 0; k < CDIM; k++) { vv[k] = cb[i * CDIM + k]; s = fmaf(vv[k], vv[k], s); }
        float n = fmaxf(sqrtf(s), 1e-12f);
        float inv = 1.f / n;
#pragma unroll
        for (int k = 0; k < CDIM; k++)
            g_cbn2[(i >> 1) * 16 + k * 2 + (i & 1)] = vv[k] * inv;
    }
}

// ---------------------------------------------------------------------------
// Main fused kernel. Block: 256 threads = 2 halves (h) x 128 t-positions.
//   phase 1: z_e (each half sums 512 d's, combine via smem)
//   phase 2: cosine argmax (each half scans 512 codes, combine via smem)
//   phase 3: out-proj (each half emits 512 d rows)
// 32KB smem buffer time-shared: winT -> cbn2 -> wout2.
// ---------------------------------------------------------------------------
__global__ void __launch_bounds__(NTHREADS, 4)
vq_main(const float* __restrict__ z,
        const float* __restrict__ in_b,
        const float* __restrict__ out_b,
        const float* __restrict__ codebook,
        float* __restrict__ out) {
    __shared__ __align__(16) float s_w[DD * CDIM];        // 32 KB
    __shared__ __align__(16) float s_x[2 * TILE * CDIM];  // 8 KB: partials / bias
    __shared__ float s_bestv[2 * TILE];
    __shared__ int   s_besti[2 * TILE];
    __shared__ float s_red[4];

    const int tid  = threadIdx.x;
    const int tl   = tid & (TILE - 1);
    const int h    = tid >> 7;            // 0 or 1
    const int blk  = blockIdx.x;
    const int b    = blk / TILES_PER_B;
    const int t    = (blk % TILES_PER_B) * TILE + tl;

    // --- stage in-proj weight (transposed) ---
    {
        const float4* src = (const float4*)g_winT;
        float4* dst = (float4*)s_w;
        for (int i = tid; i < DD * CDIM / 4; i += NTHREADS) dst[i] = src[i];
    }
    __syncthreads();

    // --- phase 1: partial z_e over this half's 512 d's (f32x2 packed) ---
    u64 a0 = 0, a1 = 0, a2 = 0, a3 = 0;
    {
        const float* zp = z + (size_t)b * (DD * TT) + (size_t)h * HALF * TT + t;
        const float* wr = s_w + h * HALF * CDIM;
#pragma unroll 4
        for (int d = 0; d < HALF; d++) {
            float zv = __ldg(zp + (size_t)d * TT);
            u64 zz = pk(zv, zv);
            const ulonglong2* w2 = (const ulonglong2*)(wr + d * CDIM);
            ulonglong2 q0 = w2[0];
            ulonglong2 q1 = w2[1];
            a0 = f2(q0.x, zz, a0);
            a1 = f2(q0.y, zz, a1);
            a2 = f2(q1.x, zz, a2);
            a3 = f2(q1.y, zz, a3);
        }
    }
    float part[CDIM];
    upk(part[0], part[1], a0);
    upk(part[2], part[3], a1);
    upk(part[4], part[5], a2);
    upk(part[6], part[7], a3);

    // publish partials, combine: both halves get full z_e
    {
        float4* myp = (float4*)(s_x + (h * TILE + tl) * CDIM);
        myp[0] = make_float4(part[0], part[1], part[2], part[3]);
        myp[1] = make_float4(part[4], part[5], part[6], part[7]);
    }
    __syncthreads();
    float ze[CDIM];
    {
        const float* oth = s_x + ((1 - h) * TILE + tl) * CDIM;
#pragma unroll
        for (int o = 0; o < CDIM; o++) ze[o] = part[o] + oth[o] + __ldg(in_b + o);
    }

    // write z_e [B, CD, T] (each half writes 4 rows, t-coalesced)
    {
        float* zeout = out + OFF_ZE + (size_t)b * (CDIM * TT) + t;
#pragma unroll
        for (int o = 0; o < 4; o++) zeout[(size_t)(h * 4 + o) * TT] = ze[h * 4 + o];
    }
    __syncthreads();   // done with winT + partials

    // --- stage pair-interleaved normalized codebook ---
    {
        const float4* src = (const float4*)g_cbn2;
        float4* dst = (float4*)s_w;
        for (int i = tid; i < CSZ * CDIM / 4; i += NTHREADS) dst[i] = src[i];
    }
    __syncthreads();

    // --- phase 2: argmax over this half's 512 codes, 2 codes per 8 FFMA2 ---
    float best = -CUDART_INF_F;
    int   bi   = 0;
    {
        u64 zz[CDIM];
#pragma unroll
        for (int k = 0; k < CDIM; k++) zz[k] = pk(ze[k], ze[k]);
        const float* cbase = s_w + h * HALF * CDIM;
#pragma unroll 4
        for (int p = 0; p < HALF / 2; p++) {
            const ulonglong2* r = (const ulonglong2*)(cbase + p * 16);
            ulonglong2 q0 = r[0], q1 = r[1], q2 = r[2], q3 = r[3];
            u64 da = 0, db = 0;
            da = f2(q0.x, zz[0], da); db = f2(q0.y, zz[1], db);
            da = f2(q1.x, zz[2], da); db = f2(q1.y, zz[3], db);
            da = f2(q2.x, zz[4], da); db = f2(q2.y, zz[5], db);
            da = f2(q3.x, zz[6], da); db = f2(q3.y, zz[7], db);
            float xa, ya, xb, yb;
            upk(xa, ya, da);
            upk(xb, yb, db);
            float d0 = xa + xb;
            float d1 = ya + yb;
            int c0 = h * HALF + 2 * p;
            if (d0 > best) { best = d0; bi = c0; }       // strict >: first max wins
            if (d1 > best) { best = d1; bi = c0 + 1; }
        }
    }
    s_bestv[h * TILE + tl] = best;
    s_besti[h * TILE + tl] = bi;
    __syncthreads();
    int fbi;
    {
        float b0 = s_bestv[tl], b1 = s_bestv[TILE + tl];
        int   i0 = s_besti[tl], i1 = s_besti[TILE + tl];
        fbi = (b1 > b0) ? i1 : i0;   // lower half wins ties (first-index semantics)
    }
    if (h == 0) out[OFF_IDX + (size_t)b * TT + t] = (float)fbi;

    // gather raw codebook row (32KB -> L2/L1 resident)
    float zq[CDIM];
    {
        const float4* cb4 = (const float4*)codebook;
        float4 q0 = __ldg(cb4 + 2 * fbi);
        float4 q1 = __ldg(cb4 + 2 * fbi + 1);
        zq[0] = q0.x; zq[1] = q0.y; zq[2] = q0.z; zq[3] = q0.w;
        zq[4] = q1.x; zq[5] = q1.y; zq[6] = q1.z; zq[7] = q1.w;
    }

    // --- loss partial (h==0 only; commitment == codebook loss numerically) ---
    if (h == 0) {
        float ls = 0.f;
#pragma unroll
        for (int o = 0; o < CDIM; o++) {
            float d = ze[o] - zq[o];
            ls = fmaf(d, d, ls);
        }
#pragma unroll
        for (int off = 16; off > 0; off >>= 1)
            ls += __shfl_down_sync(0xffffffffu, ls, off);
        if ((tid & 31) == 0) s_red[tid >> 5] = ls;
    }
    __syncthreads();
    if (tid == 0)
        g_losspart[blk] = s_red[0] + s_red[1] + s_red[2] + s_red[3];
    __syncthreads();   // guard s_w / s_x reuse

    // --- stage pair-interleaved out-proj weight + bias ---
    {
        const float4* src = (const float4*)g_wout2;
        float4* dst = (float4*)s_w;
        for (int i = tid; i < DD * CDIM / 4; i += NTHREADS) dst[i] = src[i];
        for (int i = tid; i < DD; i += NTHREADS) s_x[i] = out_b[i];
    }
    __syncthreads();

    // --- phase 3: out rows for this half's 512 d's, 2 d's per 8 FFMA2 ---
    {
        u64 zq2[CDIM];
#pragma unroll
        for (int k = 0; k < CDIM; k++) zq2[k] = pk(zq[k], zq[k]);
        const float* wbase = s_w + h * HALF * CDIM;
        const float* bbase = s_x + h * HALF;
        float* op = out + (size_t)b * (DD * TT) + (size_t)h * HALF * TT + t;
#pragma unroll 4
        for (int p = 0; p < HALF / 2; p++) {
            const ulonglong2* r = (const ulonglong2*)(wbase + p * 16);
            ulonglong2 q0 = r[0], q1 = r[1], q2 = r[2], q3 = r[3];
            float2 bv = *(const float2*)(bbase + 2 * p);
            u64 acc = pk(bv.x, bv.y);
            acc = f2(q0.x, zq2[0], acc);
            acc = f2(q0.y, zq2[1], acc);
            acc = f2(q1.x, zq2[2], acc);
            acc = f2(q1.y, zq2[3], acc);
            acc = f2(q2.x, zq2[4], acc);
            acc = f2(q2.y, zq2[5], acc);
            acc = f2(q3.x, zq2[6], acc);
            acc = f2(q3.y, zq2[7], acc);
            float v0, v1;
            upk(v0, v1, acc);
            op[(size_t)(2 * p) * TT]     = v0;
            op[(size_t)(2 * p + 1) * TT] = v1;
        }
    }
}

// ---------------------------------------------------------------------------
// Finish: deterministic fixed-order loss reduction.
// ---------------------------------------------------------------------------
__global__ void vq_finish(float* __restrict__ out) {
    int b = threadIdx.x;
    if (b < BB) {
        float s = 0.f;
        for (int i = 0; i < TILES_PER_B; i++) s += g_losspart[b * TILES_PER_B + i];
        s *= (1.0f / (float)(CDIM * TT));
        out[OFF_CL + b] = s;
        out[OFF_CB + b] = s;
    }
}

extern "C" void kernel_launch(void* const* d_in, const int* in_sizes, int n_in,
                              void* d_out, int out_size) {
    const float* z   = (const float*)d_in[0];
    const float* ipv = (const float*)d_in[1];
    const float* ipg = (const float*)d_in[2];
    const float* ipb = (const float*)d_in[3];
    const float* opv = (const float*)d_in[4];
    const float* opg = (const float*)d_in[5];
    const float* opb = (const float*)d_in[6];
    const float* cb  = (const float*)d_in[7];
    float* out = (float*)d_out;

    prep_win<<<CDIM, 256>>>(ipv, ipg);
    prep_rows<<<(CSZ + 255) / 256, 256>>>(opv, opg, cb);
    vq_main<<<NBLOCKS, NTHREADS>>>(z, ipb, opb, cb, out);
    vq_finish<<<1, 32>>>(out);
}

// round 3
// speedup vs baseline: 1.7679x; 1.2458x over previous
#include <cuda_runtime.h>
#include <math_constants.h>

// Problem constants
#define BB   16
#define DD   1024
#define TT   4096
#define CDIM 8
#define CSZ  1024

#define NTHREADS 256
#define NQ   4                     // quarters (d-split / code-split)
#define SLOTS 64                   // thread slots per quarter
#define TV   2                     // t-columns per thread
#define TILE (SLOTS * TV)          // 128 t per block
#define DQ   (DD / NQ)             // 256 d per quarter
#define CQ   (CSZ / NQ)            // 256 codes per quarter
#define TILES_PER_B (TT / TILE)    // 32
#define NBLOCKS (BB * TILES_PER_B) // 512

// Output layout (concatenated float32):
// out [B,D,T], commitment_loss [B], codebook_loss [B], indices [B,T], z_e [B,CD,T]
#define OFF_CL  (BB * DD * TT)
#define OFF_CB  (OFF_CL + BB)
#define OFF_IDX (OFF_CB + BB)
#define OFF_ZE  (OFF_IDX + BB * TT)

// Device-global scratch (no allocations allowed)
__device__ float g_winT[DD * CDIM];   // in-proj weight transposed [d][k]
__device__ float g_wout[DD * CDIM];   // out-proj weight [d][k]
__device__ float g_cbn[CSZ * CDIM];   // normalized codebook [c][k]
__device__ float g_losspart[NBLOCKS];

// ---------------- f32x2 packed helpers ----------------
typedef unsigned long long u64;

__device__ __forceinline__ u64 pk(float lo, float hi) {
    u64 r; asm("mov.b64 %0, {%1, %2};" : "=l"(r) : "f"(lo), "f"(hi)); return r;
}
__device__ __forceinline__ void upk(float& lo, float& hi, u64 v) {
    asm("mov.b64 {%0, %1}, %2;" : "=f"(lo), "=f"(hi) : "l"(v));
}
__device__ __forceinline__ u64 f2(u64 a, u64 b, u64 c) {
    u64 d; asm("fma.rn.f32x2 %0, %1, %2, %3;" : "=l"(d) : "l"(a), "l"(b), "l"(c)); return d;
}
__device__ __forceinline__ u64 a2(u64 a, u64 b) {
    u64 d; asm("add.rn.f32x2 %0, %1, %2;" : "=l"(d) : "l"(a), "l"(b)); return d;
}

// ---------------------------------------------------------------------------
// Merged prep: blocks 0..7  -> weight-norm in_proj row o (norm over D), transpose
//              blocks 8..11 -> weight-norm out_proj rows + l2-norm codebook
// ---------------------------------------------------------------------------
__global__ void vq_prep(const float* __restrict__ ipv, const float* __restrict__ ipg,
                        const float* __restrict__ opv, const float* __restrict__ opg,
                        const float* __restrict__ cb) {
    if (blockIdx.x < CDIM) {
        int o = blockIdx.x;
        __shared__ float red[256];
        float s = 0.f;
        for (int d = threadIdx.x; d < DD; d += blockDim.x) {
            float x = ipv[o * DD + d];
            s = fmaf(x, x, s);
        }
        red[threadIdx.x] = s;
        __syncthreads();
        for (int off = 128; off > 0; off >>= 1) {
            if (threadIdx.x < off) red[threadIdx.x] += red[threadIdx.x + off];
            __syncthreads();
        }
        float scale = ipg[o] / sqrtf(red[0]);
        for (int d = threadIdx.x; d < DD; d += blockDim.x)
            g_winT[d * CDIM + o] = ipv[o * DD + d] * scale;
    } else {
        int i = (blockIdx.x - CDIM) * 256 + threadIdx.x;
        if (i < DD) {
            float vv[CDIM];
            float s = 0.f;
#pragma unroll
            for (int c = 0; c < CDIM; c++) { vv[c] = opv[i * CDIM + c]; s = fmaf(vv[c], vv[c], s); }
            float sc = opg[i] / sqrtf(s);
#pragma unroll
            for (int c = 0; c < CDIM; c++) g_wout[i * CDIM + c] = vv[c] * sc;
        }
        if (i < CSZ) {
            float vv[CDIM];
            float s = 0.f;
#pragma unroll
            for (int k = 0; k < CDIM; k++) { vv[k] = cb[i * CDIM + k]; s = fmaf(vv[k], vv[k], s); }
            float inv = 1.f / fmaxf(sqrtf(s), 1e-12f);
#pragma unroll
            for (int k = 0; k < CDIM; k++) g_cbn[i * CDIM + k] = vv[k] * inv;
        }
    }
}

// ---------------------------------------------------------------------------
// Main fused kernel. 256 threads = 4 quarters (q) x 64 slots; each slot owns
// 2 adjacent t-columns (TV=2). Quarters split d-space (phases 1,3) and
// code-space (phase 2); combine through smem.
// Accumulators are f32x2 over (k,k+1) pairs in natural row layout.
// Dynamic smem: s_w (32KB weight stage, time-shared) + 16KB exchange region.
// ---------------------------------------------------------------------------
__global__ void __launch_bounds__(NTHREADS, 4)
vq_main(const float* __restrict__ z,
        const float* __restrict__ in_b,
        const float* __restrict__ out_b,
        const float* __restrict__ codebook,
        float* __restrict__ out) {
    extern __shared__ __align__(16) char smem[];
    float* s_w  = (float*)smem;                    // 32 KB: winT -> cbn -> wout
    u64*   s_ex = (u64*)(smem + 32768);            // 16 KB exchange:
    float* s_best = (float*)s_ex;                  //   [NQ][TILE] floats (2 KB)
    int*   s_bi   = (int*)s_ex + NQ * TILE;        //   [NQ][TILE] ints   (2 KB)
    float* s_bias = (float*)s_ex + 2 * NQ * TILE;  //   [DD] floats (4 KB)
    float* s_red  = (float*)(smem + 32768 + 12288);//   2 floats

    const int tid  = threadIdx.x;
    const int q    = tid >> 6;          // quarter 0..3
    const int slot = tid & (SLOTS - 1); // 0..63
    const int blk  = blockIdx.x;
    const int b    = blk / TILES_PER_B;
    const int t0   = (blk % TILES_PER_B) * TILE + slot * TV;

    // ---- stage in-proj weight (transposed) ----
    {
        const float4* src = (const float4*)g_winT;
        float4* dst = (float4*)s_w;
        for (int i = tid; i < DD * CDIM / 4; i += NTHREADS) dst[i] = src[i];
    }
    __syncthreads();

    // ---- phase 1: partial z_e over this quarter's 256 d's, 2 columns ----
    u64 aA[4] = {0, 0, 0, 0};
    u64 aB[4] = {0, 0, 0, 0};
    {
        const float* zp = z + (size_t)b * (DD * TT) + (size_t)(q * DQ) * TT + t0;
        const float* wr = s_w + q * DQ * CDIM;
#pragma unroll 4
        for (int d = 0; d < DQ; d++) {
            float2 zv = __ldg((const float2*)(zp + (size_t)d * TT));
            u64 za = pk(zv.x, zv.x);
            u64 zb = pk(zv.y, zv.y);
            const ulonglong2* w2 = (const ulonglong2*)(wr + d * CDIM);
            ulonglong2 w01 = w2[0];
            ulonglong2 w23 = w2[1];
            aA[0] = f2(w01.x, za, aA[0]);  aB[0] = f2(w01.x, zb, aB[0]);
            aA[1] = f2(w01.y, za, aA[1]);  aB[1] = f2(w01.y, zb, aB[1]);
            aA[2] = f2(w23.x, za, aA[2]);  aB[2] = f2(w23.x, zb, aB[2]);
            aA[3] = f2(w23.y, za, aA[3]);  aB[3] = f2(w23.y, zb, aB[3]);
        }
    }
    // publish partials: layout [j][col][q][slot]
#pragma unroll
    for (int j = 0; j < 4; j++) {
        s_ex[((j * 2 + 0) * NQ + q) * SLOTS + slot] = aA[j];
        s_ex[((j * 2 + 1) * NQ + q) * SLOTS + slot] = aB[j];
    }
    __syncthreads();

    // combine quarters (in order) + bias; every thread gets full ze (packed k-pairs)
    u64 zeA[4], zeB[4];
    {
        const float2* bb = (const float2*)in_b;
#pragma unroll
        for (int j = 0; j < 4; j++) {
            float2 bj = __ldg(bb + j);
            u64 bp = pk(bj.x, bj.y);
            u64 sa = s_ex[((j * 2 + 0) * NQ + 0) * SLOTS + slot];
            u64 sb = s_ex[((j * 2 + 1) * NQ + 0) * SLOTS + slot];
#pragma unroll
            for (int qq = 1; qq < NQ; qq++) {
                sa = a2(sa, s_ex[((j * 2 + 0) * NQ + qq) * SLOTS + slot]);
                sb = a2(sb, s_ex[((j * 2 + 1) * NQ + qq) * SLOTS + slot]);
            }
            zeA[j] = a2(sa, bp);
            zeB[j] = a2(sb, bp);
        }
    }

    // write z_e [B, CD, T] (quarter 0 only; t-pairs -> STG.64)
    if (q == 0) {
        float* zeo = out + OFF_ZE + (size_t)b * (CDIM * TT) + t0;
#pragma unroll
        for (int j = 0; j < 4; j++) {
            float a0, a1, b0, b1;
            upk(a0, a1, zeA[j]);
            upk(b0, b1, zeB[j]);
            *(float2*)(zeo + (size_t)(2 * j) * TT)     = make_float2(a0, b0);
            *(float2*)(zeo + (size_t)(2 * j + 1) * TT) = make_float2(a1, b1);
        }
    }
    __syncthreads();   // done with winT + partials

    // ---- stage normalized codebook ----
    {
        const float4* src = (const float4*)g_cbn;
        float4* dst = (float4*)s_w;
        for (int i = tid; i < CSZ * CDIM / 4; i += NTHREADS) dst[i] = src[i];
    }
    __syncthreads();

    // ---- phase 2: argmax over this quarter's 256 codes, both columns ----
    float bestA = -CUDART_INF_F, bestB = -CUDART_INF_F;
    int biA = 0, biB = 0;
    {
        const float* cbase = s_w + q * CQ * CDIM;
#pragma unroll 2
        for (int cc = 0; cc < CQ; cc++) {
            const ulonglong2* r = (const ulonglong2*)(cbase + cc * CDIM);
            ulonglong2 c01 = r[0];
            ulonglong2 c23 = r[1];
            u64 da = 0, db = 0;
            da = f2(c01.x, zeA[0], da);  db = f2(c01.x, zeB[0], db);
            da = f2(c01.y, zeA[1], da);  db = f2(c01.y, zeB[1], db);
            da = f2(c23.x, zeA[2], da);  db = f2(c23.x, zeB[2], db);
            da = f2(c23.y, zeA[3], da);  db = f2(c23.y, zeB[3], db);
            float la, ha, lb, hb;
            upk(la, ha, da);
            upk(lb, hb, db);
            float dotA = la + ha;
            float dotB = lb + hb;
            int c = q * CQ + cc;
            if (dotA > bestA) { bestA = dotA; biA = c; }   // strict >: first max wins
            if (dotB > bestB) { bestB = dotB; biB = c; }
        }
    }
    s_best[q * TILE + slot * 2]     = bestA;
    s_best[q * TILE + slot * 2 + 1] = bestB;
    s_bi[q * TILE + slot * 2]       = biA;
    s_bi[q * TILE + slot * 2 + 1]   = biB;
    __syncthreads();

    // combine across quarters (ascending q preserves first-index semantics)
    int fbiA, fbiB;
    {
        float vA = s_best[slot * 2], vB = s_best[slot * 2 + 1];
        fbiA = s_bi[slot * 2];  fbiB = s_bi[slot * 2 + 1];
#pragma unroll
        for (int qq = 1; qq < NQ; qq++) {
            float wA = s_best[qq * TILE + slot * 2];
            float wB = s_best[qq * TILE + slot * 2 + 1];
            if (wA > vA) { vA = wA; fbiA = s_bi[qq * TILE + slot * 2]; }
            if (wB > vB) { vB = wB; fbiB = s_bi[qq * TILE + slot * 2 + 1]; }
        }
    }
    if (q == 0)
        *(float2*)(out + OFF_IDX + (size_t)b * TT + t0) = make_float2((float)fbiA, (float)fbiB);

    // gather raw codebook rows (32KB -> L1/L2 resident)
    float4 qa0, qa1, qb0, qb1;
    {
        const float4* cb4 = (const float4*)codebook;
        qa0 = __ldg(cb4 + 2 * fbiA);
        qa1 = __ldg(cb4 + 2 * fbiA + 1);
        qb0 = __ldg(cb4 + 2 * fbiB);
        qb1 = __ldg(cb4 + 2 * fbiB + 1);
    }

    // ---- loss partial (quarter 0 only; commitment == codebook numerically) ----
    if (q == 0) {
        float zqa[CDIM] = {qa0.x, qa0.y, qa0.z, qa0.w, qa1.x, qa1.y, qa1.z, qa1.w};
        float zqb[CDIM] = {qb0.x, qb0.y, qb0.z, qb0.w, qb1.x, qb1.y, qb1.z, qb1.w};
        float ls = 0.f;
#pragma unroll
        for (int j = 0; j < 4; j++) {
            float a0, a1, b0, b1;
            upk(a0, a1, zeA[j]);
            upk(b0, b1, zeB[j]);
            float d0 = a0 - zqa[2 * j], d1 = a1 - zqa[2 * j + 1];
            float d2 = b0 - zqb[2 * j], d3 = b1 - zqb[2 * j + 1];
            ls = fmaf(d0, d0, ls);
            ls = fmaf(d1, d1, ls);
            ls = fmaf(d2, d2, ls);
            ls = fmaf(d3, d3, ls);
        }
#pragma unroll
        for (int off = 16; off > 0; off >>= 1)
            ls += __shfl_down_sync(0xffffffffu, ls, off);
        if ((tid & 31) == 0) s_red[tid >> 5] = ls;
    }
    __syncthreads();
    if (tid == 0) g_losspart[blk] = s_red[0] + s_red[1];

    // ---- stage out-proj weight + bias ----
    {
        const float4* src = (const float4*)g_wout;
        float4* dst = (float4*)s_w;
        for (int i = tid; i < DD * CDIM / 4; i += NTHREADS) dst[i] = src[i];
        for (int i = tid; i < DD; i += NTHREADS) s_bias[i] = __ldg(out_b + i);
    }
    __syncthreads();

    // ---- phase 3: out rows for this quarter's 256 d's, both columns ----
    {
        u64 zqA[4] = { pk(qa0.x, qa0.y), pk(qa0.z, qa0.w), pk(qa1.x, qa1.y), pk(qa1.z, qa1.w) };
        u64 zqB[4] = { pk(qb0.x, qb0.y), pk(qb0.z, qb0.w), pk(qb1.x, qb1.y), pk(qb1.z, qb1.w) };
        const float* wr = s_w + q * DQ * CDIM;
        const float* br = s_bias + q * DQ;
        float* op = out + (size_t)b * (DD * TT) + (size_t)(q * DQ) * TT + t0;
#pragma unroll 2
        for (int d = 0; d < DQ; d++) {
            const ulonglong2* w2 = (const ulonglong2*)(wr + d * CDIM);
            ulonglong2 w01 = w2[0];
            ulonglong2 w23 = w2[1];
            float bd = br[d];
            u64 acA = pk(bd, 0.f);
            u64 acB = pk(bd, 0.f);
            acA = f2(w01.x, zqA[0], acA);  acB = f2(w01.x, zqB[0], acB);
            acA = f2(w01.y, zqA[1], acA);  acB = f2(w01.y, zqB[1], acB);
            acA = f2(w23.x, zqA[2], acA);  acB = f2(w23.x, zqB[2], acB);
            acA = f2(w23.y, zqA[3], acA);  acB = f2(w23.y, zqB[3], acB);
            float la, ha, lb, hb;
            upk(la, ha, acA);
            upk(lb, hb, acB);
            *(float2*)(op + (size_t)d * TT) = make_float2(la + ha, lb + hb);
        }
    }
}

// ---------------------------------------------------------------------------
// Finish: deterministic fixed-order loss reduction.
// ---------------------------------------------------------------------------
__global__ void vq_finish(float* __restrict__ out) {
    int b = threadIdx.x;
    if (b < BB) {
        float s = 0.f;
        for (int i = 0; i < TILES_PER_B; i++) s += g_losspart[b * TILES_PER_B + i];
        s *= (1.0f / (float)(CDIM * TT));
        out[OFF_CL + b] = s;
        out[OFF_CB + b] = s;
    }
}

extern "C" void kernel_launch(void* const* d_in, const int* in_sizes, int n_in,
                              void* d_out, int out_size) {
    const float* z   = (const float*)d_in[0];
    const float* ipv = (const float*)d_in[1];
    const float* ipg = (const float*)d_in[2];
    const float* ipb = (const float*)d_in[3];
    const float* opv = (const float*)d_in[4];
    const float* opg = (const float*)d_in[5];
    const float* opb = (const float*)d_in[6];
    const float* cb  = (const float*)d_in[7];
    float* out = (float*)d_out;

    const int smem_bytes = 32768 + 16384;  // s_w + exchange
    cudaFuncSetAttribute(vq_main, cudaFuncAttributeMaxDynamicSharedMemorySize, smem_bytes);

    vq_prep<<<CDIM + 4, 256>>>(ipv, ipg, opv, opg, cb);
    vq_main<<<NBLOCKS, NTHREADS, smem_bytes>>>(z, ipb, opb, cb, out);
    vq_finish<<<1, 32>>>(out);
}